// round 1
// baseline (speedup 1.0000x reference)
#include <cuda_runtime.h>
#include <mma.h>
#include <math.h>

using namespace nvcuda;

// Problem constants
constexpr int B_   = 2;
constexpr int S_   = 2048;
constexpr int DIM_ = 4096;
constexpr int NH_  = 32;
constexpr int NKV_ = 8;
constexpr int HD_  = 128;

// GEMM tiling
constexpr int BM = 128;
constexpr int BN = 64;
constexpr int KC = 32;

// Scratch (module-scope device arrays; allocation-free at launch time)
__device__ float g_q[(size_t)B_ * S_ * NH_ * HD_];        //  64 MB  [b,s,h,d]
__device__ float g_k[(size_t)B_ * S_ * NKV_ * HD_];       //  16 MB  [b,s,kh,d]
__device__ float g_v[(size_t)B_ * S_ * NKV_ * HD_];       //  16 MB  [b,s,kh,d]
__device__ float g_attn[(size_t)B_ * S_ * NH_ * HD_];     //  64 MB  [b,s,h,d]
__device__ float g_scores[(size_t)B_ * NH_ * S_ * S_];    // 1.07 GB [b,h,q,k]

// ---------------------------------------------------------------------------
// Generic batched GEMM:
//   BT = true :  C[m,n] = scale * sum_k A[m,k] * B[n,k]   (B row-major [N,K])
//   BT = false:  C[m,n] = scale * sum_k A[m,k] * B[k,n]   (B row-major [K,N])
// 3xTF32 (hi/lo split) for ~fp32 accuracy on tensor cores.
// Batch (blockIdx.z): z2 = z/zdiv, z1 = z%zdiv; per-operand strides; B also
// divided by bdiv for GQA head sharing.
// causal=1: skip tiles strictly above the diagonal (cols all > rows).
// ---------------------------------------------------------------------------
template <bool BT>
__global__ __launch_bounds__(256)
void gemm_k(const float* __restrict__ A, const float* __restrict__ Bm,
            float* __restrict__ C,
            int K, int lda, int ldb, int ldc,
            int zdiv, int bdiv,
            long long sA1, long long sA2,
            long long sB1, long long sB2,
            long long sC1, long long sC2,
            float scale, int causal)
{
    const int bm0 = blockIdx.y * BM;
    const int bn0 = blockIdx.x * BN;
    if (causal && bn0 > bm0 + (BM - 1)) return;   // tile fully masked

    const int z  = blockIdx.z;
    const int z2 = z / zdiv;
    const int z1 = z - z2 * zdiv;
    A  += z2 * sA2 + (long long)z1 * sA1;
    Bm += z2 * sB2 + (long long)(z1 / bdiv) * sB1;
    C  += z2 * sC2 + (long long)z1 * sC1;

    __shared__ float As[BM * 36];   // [128][32] padded to 36
    __shared__ float Bs[2304];      // BT: [64][36]; !BT: [32][68]

    const int tid = threadIdx.x;
    const int w   = tid >> 5;
    const int wm  = w & 3;    // warp row  (4 x 32 = 128)
    const int wn  = w >> 2;   // warp col  (2 x 32 = 64)

    wmma::fragment<wmma::accumulator, 16, 16, 8, float> acc[2][2];
    #pragma unroll
    for (int i = 0; i < 2; i++)
        #pragma unroll
        for (int j = 0; j < 2; j++)
            wmma::fill_fragment(acc[i][j], 0.0f);

    for (int kc = 0; kc < K; kc += KC) {
        // Stage A tile: 128 x 32 floats = 1024 float4, 4 per thread
        #pragma unroll
        for (int r = 0; r < 4; r++) {
            int jj  = tid + r * 256;
            int row = jj >> 3;
            int k4  = jj & 7;
            *(float4*)&As[row * 36 + k4 * 4] =
                *(const float4*)(A + (long long)(bm0 + row) * lda + kc + k4 * 4);
        }
        // Stage B tile: 512 float4, 2 per thread
        if (BT) {
            #pragma unroll
            for (int r = 0; r < 2; r++) {
                int jj  = tid + r * 256;
                int row = jj >> 3;          // n within tile
                int k4  = jj & 7;
                *(float4*)&Bs[row * 36 + k4 * 4] =
                    *(const float4*)(Bm + (long long)(bn0 + row) * ldb + kc + k4 * 4);
            }
        } else {
            #pragma unroll
            for (int r = 0; r < 2; r++) {
                int jj  = tid + r * 256;
                int row = jj >> 4;          // k within tile
                int n4  = jj & 15;
                *(float4*)&Bs[row * 68 + n4 * 4] =
                    *(const float4*)(Bm + (long long)(kc + row) * ldb + bn0 + n4 * 4);
            }
        }
        __syncthreads();

        #pragma unroll
        for (int kk = 0; kk < 4; kk++) {
            wmma::fragment<wmma::matrix_a, 16, 16, 8, wmma::precision::tf32,
                           wmma::row_major> ahi[2], alo[2];
            #pragma unroll
            for (int i = 0; i < 2; i++) {
                wmma::load_matrix_sync(ahi[i], &As[(wm * 32 + i * 16) * 36 + kk * 8], 36);
                #pragma unroll
                for (int e = 0; e < ahi[i].num_elements; e++) {
                    float v = ahi[i].x[e];
                    float h = wmma::__float_to_tf32(v);
                    ahi[i].x[e] = h;
                    alo[i].x[e] = wmma::__float_to_tf32(v - h);
                }
            }
            if constexpr (BT) {
                wmma::fragment<wmma::matrix_b, 16, 16, 8, wmma::precision::tf32,
                               wmma::col_major> bhi[2], blo[2];
                #pragma unroll
                for (int j = 0; j < 2; j++) {
                    wmma::load_matrix_sync(bhi[j], &Bs[(wn * 32 + j * 16) * 36 + kk * 8], 36);
                    #pragma unroll
                    for (int e = 0; e < bhi[j].num_elements; e++) {
                        float v = bhi[j].x[e];
                        float h = wmma::__float_to_tf32(v);
                        bhi[j].x[e] = h;
                        blo[j].x[e] = wmma::__float_to_tf32(v - h);
                    }
                }
                #pragma unroll
                for (int i = 0; i < 2; i++)
                    #pragma unroll
                    for (int j = 0; j < 2; j++) {
                        wmma::mma_sync(acc[i][j], ahi[i], bhi[j], acc[i][j]);
                        wmma::mma_sync(acc[i][j], ahi[i], blo[j], acc[i][j]);
                        wmma::mma_sync(acc[i][j], alo[i], bhi[j], acc[i][j]);
                    }
            } else {
                wmma::fragment<wmma::matrix_b, 16, 16, 8, wmma::precision::tf32,
                               wmma::row_major> bhi[2], blo[2];
                #pragma unroll
                for (int j = 0; j < 2; j++) {
                    wmma::load_matrix_sync(bhi[j], &Bs[(kk * 8) * 68 + wn * 32 + j * 16], 68);
                    #pragma unroll
                    for (int e = 0; e < bhi[j].num_elements; e++) {
                        float v = bhi[j].x[e];
                        float h = wmma::__float_to_tf32(v);
                        bhi[j].x[e] = h;
                        blo[j].x[e] = wmma::__float_to_tf32(v - h);
                    }
                }
                #pragma unroll
                for (int i = 0; i < 2; i++)
                    #pragma unroll
                    for (int j = 0; j < 2; j++) {
                        wmma::mma_sync(acc[i][j], ahi[i], bhi[j], acc[i][j]);
                        wmma::mma_sync(acc[i][j], ahi[i], blo[j], acc[i][j]);
                        wmma::mma_sync(acc[i][j], alo[i], bhi[j], acc[i][j]);
                    }
            }
        }
        __syncthreads();
    }

    #pragma unroll
    for (int i = 0; i < 2; i++)
        #pragma unroll
        for (int j = 0; j < 2; j++) {
            #pragma unroll
            for (int e = 0; e < acc[i][j].num_elements; e++)
                acc[i][j].x[e] *= scale;
            wmma::store_matrix_sync(
                C + (long long)(bm0 + wm * 32 + i * 16) * ldc + bn0 + wn * 32 + j * 16,
                acc[i][j], ldc, wmma::mem_row_major);
        }
}

// ---------------------------------------------------------------------------
// Causal softmax over one row of scores. Reads only n <= q; writes zeros for
// n > q (covers tiles the GEMM skipped, and implements the causal mask).
// ---------------------------------------------------------------------------
__global__ __launch_bounds__(256)
void softmax_k(float* __restrict__ sc)
{
    const long long row = blockIdx.x;            // [0, B*NH*S)
    const int q = (int)(row % S_);
    float* p = sc + row * (long long)S_;
    const int L = q + 1;
    const int tid = threadIdx.x;
    __shared__ float red[8];

    float m = -1e30f;
    for (int i = tid; i < L; i += 256) m = fmaxf(m, p[i]);
    #pragma unroll
    for (int o = 16; o; o >>= 1) m = fmaxf(m, __shfl_xor_sync(0xffffffffu, m, o));
    if ((tid & 31) == 0) red[tid >> 5] = m;
    __syncthreads();
    m = red[0];
    #pragma unroll
    for (int i = 1; i < 8; i++) m = fmaxf(m, red[i]);
    __syncthreads();

    float s = 0.0f;
    for (int i = tid; i < L; i += 256) s += expf(p[i] - m);
    #pragma unroll
    for (int o = 16; o; o >>= 1) s += __shfl_xor_sync(0xffffffffu, s, o);
    if ((tid & 31) == 0) red[tid >> 5] = s;
    __syncthreads();
    s = red[0];
    #pragma unroll
    for (int i = 1; i < 8; i++) s += red[i];

    const float inv = 1.0f / s;
    for (int i = tid; i < L; i += 256) p[i] = expf(p[i] - m) * inv;
    for (int i = L + tid; i < S_; i += 256) p[i] = 0.0f;
}

// ---------------------------------------------------------------------------
// RoPE in-place on [B, S, nh, HD] with interleaved (even, odd) pairs.
// ---------------------------------------------------------------------------
__global__ __launch_bounds__(256)
void rope_k(float* __restrict__ t, int nh,
            const float* __restrict__ cs, const float* __restrict__ sn)
{
    long long idx = (long long)blockIdx.x * 256 + threadIdx.x;
    const long long total = (long long)B_ * S_ * nh * (HD_ / 2);
    if (idx >= total) return;
    const int i = (int)(idx & 63);       // HD/2 = 64
    long long r = idx >> 6;
    const int h = (int)(r % nh); r /= nh;
    const int s = (int)(r % S_);
    const long long b = r / S_;

    const float c  = cs[s * 64 + i];
    const float si = sn[s * 64 + i];
    float* base = t + (((b * S_ + s) * nh + h) * (long long)HD_) + 2 * i;
    const float t0 = base[0];
    const float t1 = base[1];
    base[0] = t0 * c - t1 * si;
    base[1] = t0 * si + t1 * c;
}

// ---------------------------------------------------------------------------
// Inputs (metadata order): x, wq, wk, wv, wo, freqs_cos, freqs_sin
// ---------------------------------------------------------------------------
extern "C" void kernel_launch(void* const* d_in, const int* in_sizes, int n_in,
                              void* d_out, int out_size)
{
    const float* x  = (const float*)d_in[0];
    const float* wq = (const float*)d_in[1];
    const float* wk = (const float*)d_in[2];
    const float* wv = (const float*)d_in[3];
    const float* wo = (const float*)d_in[4];
    const float* fc = (const float*)d_in[5];
    const float* fs = (const float*)d_in[6];
    float* out = (float*)d_out;

    float *qp, *kp, *vp, *ap, *sp;
    cudaGetSymbolAddress((void**)&qp, g_q);
    cudaGetSymbolAddress((void**)&kp, g_k);
    cudaGetSymbolAddress((void**)&vp, g_v);
    cudaGetSymbolAddress((void**)&ap, g_attn);
    cudaGetSymbolAddress((void**)&sp, g_scores);

    const int M = B_ * S_;                       // 4096 tokens
    const float scale = 0.08838834764831845f;    // 1/sqrt(128)

    // Q / K / V projections: C = x * W^T
    gemm_k<true><<<dim3(DIM_ / BN, M / BM, 1), 256>>>(
        x, wq, qp, DIM_, DIM_, DIM_, DIM_,
        1, 1, 0, 0, 0, 0, 0, 0, 1.0f, 0);
    gemm_k<true><<<dim3((NKV_ * HD_) / BN, M / BM, 1), 256>>>(
        x, wk, kp, DIM_, DIM_, DIM_, NKV_ * HD_,
        1, 1, 0, 0, 0, 0, 0, 0, 1.0f, 0);
    gemm_k<true><<<dim3((NKV_ * HD_) / BN, M / BM, 1), 256>>>(
        x, wv, vp, DIM_, DIM_, DIM_, NKV_ * HD_,
        1, 1, 0, 0, 0, 0, 0, 0, 1.0f, 0);

    // RoPE on Q and K
    rope_k<<<(B_ * S_ * NH_ * (HD_ / 2) + 255) / 256, 256>>>(qp, NH_, fc, fs);
    rope_k<<<(B_ * S_ * NKV_ * (HD_ / 2) + 255) / 256, 256>>>(kp, NKV_, fc, fs);

    // scores[b,h] = scale * Q[b,h] * K[b,h/4]^T  (causal tile-skip)
    gemm_k<true><<<dim3(S_ / BN, S_ / BM, B_ * NH_), 256>>>(
        qp, kp, sp, HD_,
        NH_ * HD_, NKV_ * HD_, S_,
        NH_, 4,
        (long long)HD_, (long long)S_ * NH_ * HD_,
        (long long)HD_, (long long)S_ * NKV_ * HD_,
        (long long)S_ * S_, (long long)NH_ * S_ * S_,
        scale, 1);

    // causal softmax (also zero-fills masked region)
    softmax_k<<<B_ * NH_ * S_, 256>>>(sp);

    // attn[b,h] = P[b,h] * V[b,h/4]
    gemm_k<false><<<dim3(HD_ / BN, S_ / BM, B_ * NH_), 256>>>(
        sp, vp, ap, S_,
        S_, NKV_ * HD_, NH_ * HD_,
        NH_, 4,
        (long long)S_ * S_, (long long)NH_ * S_ * S_,
        (long long)HD_, (long long)S_ * NKV_ * HD_,
        (long long)HD_, (long long)S_ * NH_ * HD_,
        1.0f, 0);

    // output projection: out = attn * wo^T
    gemm_k<true><<<dim3(DIM_ / BN, M / BM, 1), 256>>>(
        ap, wo, out, DIM_, DIM_, DIM_, DIM_,
        1, 1, 0, 0, 0, 0, 0, 0, 1.0f, 0);
}

// round 3
// speedup vs baseline: 4.0667x; 4.0667x over previous
#include <cuda_runtime.h>
#include <cuda_bf16.h>
#include <math.h>

// Problem constants
constexpr int B_   = 2;
constexpr int S_   = 2048;
constexpr int DIM_ = 4096;
constexpr int NH_  = 32;
constexpr int NKV_ = 8;
constexpr int HD_  = 128;

// ---------------------------------------------------------------------------
// Scratch (module-scope device arrays; allocation-free at launch time)
// ---------------------------------------------------------------------------
__device__ __nv_bfloat16 g_xhi[16777216],  g_xlo[16777216];     // x split
__device__ __nv_bfloat16 g_wqhi[16777216], g_wqlo[16777216];
__device__ __nv_bfloat16 g_wkhi[4194304],  g_wklo[4194304];
__device__ __nv_bfloat16 g_wvhi[4194304],  g_wvlo[4194304];
__device__ __nv_bfloat16 g_wohi[16777216], g_wolo[16777216];
__device__ float         g_qf[16777216];                        // q fp32 (pre-rope)
__device__ float         g_kf[4194304];
__device__ float         g_vf[4194304];
__device__ __nv_bfloat16 g_qhi[16777216], g_qlo[16777216];      // post-rope split
__device__ __nv_bfloat16 g_khi[4194304],  g_klo[4194304];
__device__ __nv_bfloat16 g_vthi[4194304], g_vtlo[4194304];      // V transposed [b,kv,d,s]
__device__ float         g_sc[268435456];                       // scores fp32 [b,h,q,k]
__device__ __nv_bfloat16 g_phi[268435456], g_plo[268435456];    // probs split
__device__ __nv_bfloat16 g_ahi[16777216],  g_alo[16777216];     // attn split [b,s,h,d]

// ---------------------------------------------------------------------------
// PTX helpers — sm_80-era only (compute_103 virtual arch: NO tcgen05)
// ---------------------------------------------------------------------------
__device__ __forceinline__ unsigned smem_u32(const void* p) {
    return (unsigned)__cvta_generic_to_shared(p);
}
__device__ __forceinline__ void cpa16(unsigned dst, const void* src) {
    asm volatile("cp.async.cg.shared.global [%0], [%1], 16;" :: "r"(dst), "l"(src) : "memory");
}
__device__ __forceinline__ void cpa_commit() {
    asm volatile("cp.async.commit_group;" ::: "memory");
}
__device__ __forceinline__ void cpa_wait1() {
    asm volatile("cp.async.wait_group 1;" ::: "memory");
}
__device__ __forceinline__ void cpa_wait0() {
    asm volatile("cp.async.wait_group 0;" ::: "memory");
}
__device__ __forceinline__ void ldsm4(unsigned* r, unsigned a) {
    asm volatile("ldmatrix.sync.aligned.m8n8.x4.shared.b16 {%0,%1,%2,%3}, [%4];"
                 : "=r"(r[0]), "=r"(r[1]), "=r"(r[2]), "=r"(r[3]) : "r"(a));
}
__device__ __forceinline__ void mma16816(float* c, const unsigned* a, const unsigned* b) {
    asm volatile("mma.sync.aligned.m16n8k16.row.col.f32.bf16.bf16.f32 "
                 "{%0,%1,%2,%3}, {%4,%5,%6,%7}, {%8,%9}, {%0,%1,%2,%3};"
                 : "+f"(c[0]), "+f"(c[1]), "+f"(c[2]), "+f"(c[3])
                 : "r"(a[0]), "r"(a[1]), "r"(a[2]), "r"(a[3]), "r"(b[0]), "r"(b[1]));
}

// SMEM geometry: rows of 32 bf16 (64B) padded to 80B pitch -> conflict-free
// ldmatrix (8-row phase banks: r*20 mod 32 all distinct) and 16B-aligned cp.async.
constexpr int PITCH   = 80;
constexpr int SUBT    = 128 * PITCH;   // 10240 B per operand subtile
constexpr int STAGE   = 4 * SUBT;      // Ahi|Alo|Bhi|Blo = 40960 B
constexpr int SMEM_SZ = 2 * STAGE;     // double buffered = 81920 B

// ---------------------------------------------------------------------------
// bf16 split GEMM via mma.sync: C[m,n] = scale * sum_k A[m,k]*B[n,k]
//   A = Ahi+Alo, B = Bhi+Blo (hi/lo split of fp32), both K-major [rows, K].
//   3 passes accumulated in fp32 regs: hi*hi + hi*lo + lo*hi.
//   EPI=0: fp32 C.  EPI=1: hi/lo bf16 split C.
//   causal=1: skip tiles above diagonal.  kcap=1: K capped at bm0+128.
// ---------------------------------------------------------------------------
template <int EPI>
__global__ __launch_bounds__(256)
void gemm_mma(const __nv_bfloat16* __restrict__ Ahi, const __nv_bfloat16* __restrict__ Alo,
              const __nv_bfloat16* __restrict__ Bhi, const __nv_bfloat16* __restrict__ Blo,
              float* __restrict__ Cf,
              __nv_bfloat16* __restrict__ Chi, __nv_bfloat16* __restrict__ Clo,
              int K, int lda, int ldb, int ldc,
              int zdiv, int bdiv,
              long long sA1, long long sA2, long long sB1, long long sB2,
              long long sC1, long long sC2,
              float scale, int causal, int kcap)
{
    const int bm0 = blockIdx.y * 128;
    const int bn0 = blockIdx.x * 128;
    if (causal && bn0 > bm0) return;

    const int z  = blockIdx.z;
    const int z2 = z / zdiv;
    const int z1 = z - z2 * zdiv;
    const __nv_bfloat16* Ah = Ahi + z2 * sA2 + (long long)z1 * sA1;
    const __nv_bfloat16* Al = Alo + z2 * sA2 + (long long)z1 * sA1;
    const __nv_bfloat16* Bh = Bhi + z2 * sB2 + (long long)(z1 / bdiv) * sB1;
    const __nv_bfloat16* Bl = Blo + z2 * sB2 + (long long)(z1 / bdiv) * sB1;
    const long long coff = z2 * sC2 + (long long)z1 * sC1;

    extern __shared__ char smem[];
    const unsigned sb = smem_u32(smem);
    const int tid  = threadIdx.x;
    const int lane = tid & 31;
    const int wid  = tid >> 5;
    const int wm   = wid & 3;     // 4 warp-rows x 32
    const int wn   = wid >> 2;    // 2 warp-cols x 64

    int Keff = K;
    if (kcap) { int c = bm0 + 128; if (c < Keff) Keff = c; }
    const int nk = Keff >> 5;     // KC = 32

    auto stage = [&](int si) {
        const unsigned base = sb + (si & 1) * STAGE;
        const int kc = si * 32;
        #pragma unroll
        for (int it = 0; it < 8; it++) {
            const int sub = it >> 1;                 // 0:Ahi 1:Alo 2:Bhi 3:Blo
            const int w   = (tid + it * 256) & 511;
            const int row = w >> 2, seg = w & 3;     // 4 x 16B per 64B row
            const __nv_bfloat16* src;
            if      (sub == 0) src = Ah + (long long)(bm0 + row) * lda + kc + seg * 8;
            else if (sub == 1) src = Al + (long long)(bm0 + row) * lda + kc + seg * 8;
            else if (sub == 2) src = Bh + (long long)(bn0 + row) * ldb + kc + seg * 8;
            else               src = Bl + (long long)(bn0 + row) * ldb + kc + seg * 8;
            cpa16(base + sub * SUBT + row * PITCH + seg * 16, src);
        }
    };

    float acc[2][8][4];
    #pragma unroll
    for (int i = 0; i < 2; i++)
        #pragma unroll
        for (int j = 0; j < 8; j++)
            #pragma unroll
            for (int e = 0; e < 4; e++) acc[i][j][e] = 0.0f;

    stage(0); cpa_commit();
    stage(1); cpa_commit();

    // ldmatrix lane address components (constant across chunks)
    const int arow = wm * 32 + (lane & 15);          // + mt*16
    const int asel = (lane >> 4);                    // 16B chunk within kstep
    const int brow = wn * 64 + (lane & 7) + ((lane >> 4) << 3);  // + pair*16
    const int bsel = (lane >> 3) & 1;

    for (int i = 0; i < nk; i++) {
        if (i + 1 < nk) cpa_wait1(); else cpa_wait0();
        __syncthreads();
        const unsigned base = sb + (i & 1) * STAGE;

        #pragma unroll
        for (int ks = 0; ks < 2; ks++) {
            unsigned ah[2][4], al[2][4];
            #pragma unroll
            for (int mt = 0; mt < 2; mt++) {
                const unsigned off = (arow + mt * 16) * PITCH + (ks * 2 + asel) * 16;
                ldsm4(ah[mt], base + off);
                ldsm4(al[mt], base + SUBT + off);
            }
            #pragma unroll
            for (int pr = 0; pr < 4; pr++) {
                unsigned bh[4], bl[4];
                const unsigned off = (brow + pr * 16) * PITCH + (ks * 2 + bsel) * 16;
                ldsm4(bh, base + 2 * SUBT + off);
                ldsm4(bl, base + 3 * SUBT + off);
                #pragma unroll
                for (int mt = 0; mt < 2; mt++)
                    #pragma unroll
                    for (int hf = 0; hf < 2; hf++) {
                        float* c = acc[mt][pr * 2 + hf];
                        mma16816(c, ah[mt], &bh[hf * 2]);
                        mma16816(c, ah[mt], &bl[hf * 2]);
                        mma16816(c, al[mt], &bh[hf * 2]);
                    }
            }
        }
        __syncthreads();
        if (i + 2 < nk) { stage(i + 2); cpa_commit(); }
    }

    // Epilogue: register accumulators -> global (float2 / bf16x2 stores)
    const int er = bm0 + wm * 32 + (lane >> 2);
    const int ec = bn0 + wn * 64 + (lane & 3) * 2;
    #pragma unroll
    for (int mt = 0; mt < 2; mt++)
        #pragma unroll
        for (int nt = 0; nt < 8; nt++) {
            const float* c = acc[mt][nt];
            const int row = er + mt * 16;
            const int col = ec + nt * 8;
            const long long gi0 = coff + (long long)row * ldc + col;
            const long long gi1 = coff + (long long)(row + 8) * ldc + col;
            if (EPI == 0) {
                *(float2*)(Cf + gi0) = make_float2(c[0] * scale, c[1] * scale);
                *(float2*)(Cf + gi1) = make_float2(c[2] * scale, c[3] * scale);
            } else {
                float v0 = c[0] * scale, v1 = c[1] * scale;
                float v2 = c[2] * scale, v3 = c[3] * scale;
                __nv_bfloat16 h0 = __float2bfloat16(v0), h1 = __float2bfloat16(v1);
                __nv_bfloat16 h2 = __float2bfloat16(v2), h3 = __float2bfloat16(v3);
                *(__nv_bfloat162*)(Chi + gi0) = __halves2bfloat162(h0, h1);
                *(__nv_bfloat162*)(Chi + gi1) = __halves2bfloat162(h2, h3);
                *(__nv_bfloat162*)(Clo + gi0) = __halves2bfloat162(
                    __float2bfloat16(v0 - __bfloat162float(h0)),
                    __float2bfloat16(v1 - __bfloat162float(h1)));
                *(__nv_bfloat162*)(Clo + gi1) = __halves2bfloat162(
                    __float2bfloat16(v2 - __bfloat162float(h2)),
                    __float2bfloat16(v3 - __bfloat162float(h3)));
            }
        }
}

// ---------------------------------------------------------------------------
// Elementwise fp32 -> (hi, lo) bf16 split
// ---------------------------------------------------------------------------
__global__ __launch_bounds__(256)
void split_k(const float4* __restrict__ s, __nv_bfloat162* __restrict__ h2,
             __nv_bfloat162* __restrict__ l2, int n4)
{
    int i = blockIdx.x * 256 + threadIdx.x;
    if (i >= n4) return;
    float4 v = s[i];
    __nv_bfloat16 hx = __float2bfloat16(v.x), hy = __float2bfloat16(v.y);
    __nv_bfloat16 hz = __float2bfloat16(v.z), hw = __float2bfloat16(v.w);
    h2[2 * i]     = __halves2bfloat162(hx, hy);
    h2[2 * i + 1] = __halves2bfloat162(hz, hw);
    l2[2 * i]     = __halves2bfloat162(__float2bfloat16(v.x - __bfloat162float(hx)),
                                       __float2bfloat16(v.y - __bfloat162float(hy)));
    l2[2 * i + 1] = __halves2bfloat162(__float2bfloat16(v.z - __bfloat162float(hz)),
                                       __float2bfloat16(v.w - __bfloat162float(hw)));
}

// ---------------------------------------------------------------------------
// RoPE + split: reads fp32 [B,S,nh,HD], writes hi/lo bf16 same layout
// ---------------------------------------------------------------------------
__global__ __launch_bounds__(256)
void rope_split_k(const float* __restrict__ t, int nh,
                  const float* __restrict__ cs, const float* __restrict__ sn,
                  __nv_bfloat16* __restrict__ hi, __nv_bfloat16* __restrict__ lo)
{
    long long idx = (long long)blockIdx.x * 256 + threadIdx.x;
    const long long total = (long long)B_ * S_ * nh * (HD_ / 2);
    if (idx >= total) return;
    const int i = (int)(idx & 63);
    long long r = idx >> 6;
    const int h = (int)(r % nh); r /= nh;
    const int s = (int)(r % S_);
    const long long b = r / S_;

    const float c  = cs[s * 64 + i];
    const float si = sn[s * 64 + i];
    const long long off = (((b * S_ + s) * nh + h) * (long long)HD_) + 2 * i;
    const float t0 = t[off], t1 = t[off + 1];
    const float o0 = t0 * c - t1 * si;
    const float o1 = t0 * si + t1 * c;
    __nv_bfloat16 h0 = __float2bfloat16(o0);
    __nv_bfloat16 h1 = __float2bfloat16(o1);
    hi[off] = h0;     lo[off]     = __float2bfloat16(o0 - __bfloat162float(h0));
    hi[off + 1] = h1; lo[off + 1] = __float2bfloat16(o1 - __bfloat162float(h1));
}

// ---------------------------------------------------------------------------
// V transpose + split: vf32 [b,s,kv,d] -> vt hi/lo [b,kv,d,s]
// ---------------------------------------------------------------------------
__global__ __launch_bounds__(256)
void tsplit_v_k(const float* __restrict__ v,
                __nv_bfloat16* __restrict__ hi, __nv_bfloat16* __restrict__ lo)
{
    __shared__ float tile[32][33];
    const int bz = blockIdx.z;
    const int b = bz >> 3, kv = bz & 7;
    const int s0 = blockIdx.x * 32, d0 = blockIdx.y * 32;
    const int tx = threadIdx.x & 31, ty = threadIdx.x >> 5;

    #pragma unroll
    for (int j = 0; j < 4; j++) {
        int s = s0 + ty + j * 8;
        tile[ty + j * 8][tx] = v[((size_t)(b * S_ + s) * NKV_ + kv) * HD_ + d0 + tx];
    }
    __syncthreads();
    #pragma unroll
    for (int j = 0; j < 4; j++) {
        int d = d0 + ty + j * 8;
        float val = tile[tx][ty + j * 8];
        size_t o = ((size_t)(b * NKV_ + kv) * HD_ + d) * S_ + s0 + tx;
        __nv_bfloat16 h = __float2bfloat16(val);
        hi[o] = h;
        lo[o] = __float2bfloat16(val - __bfloat162float(h));
    }
}

// ---------------------------------------------------------------------------
// Causal softmax: fp32 scores row -> hi/lo bf16 probs (zero-filled beyond the
// diagonal, covering skipped score tiles).
// ---------------------------------------------------------------------------
__global__ __launch_bounds__(256)
void softmax_k(const float* __restrict__ sc,
               __nv_bfloat16* __restrict__ phi, __nv_bfloat16* __restrict__ plo)
{
    const long long row = blockIdx.x;
    const int q = (int)(row % S_);
    const float* p = sc + row * (long long)S_;
    __nv_bfloat16* oh = phi + row * (long long)S_;
    __nv_bfloat16* ol = plo + row * (long long)S_;
    const int L = q + 1;
    const int tid = threadIdx.x;
    __shared__ float red[8];

    float m = -1e30f;
    for (int i = tid; i < L; i += 256) m = fmaxf(m, p[i]);
    #pragma unroll
    for (int o = 16; o; o >>= 1) m = fmaxf(m, __shfl_xor_sync(0xffffffffu, m, o));
    if ((tid & 31) == 0) red[tid >> 5] = m;
    __syncthreads();
    m = red[0];
    #pragma unroll
    for (int i = 1; i < 8; i++) m = fmaxf(m, red[i]);
    __syncthreads();

    float s = 0.0f;
    for (int i = tid; i < L; i += 256) s += expf(p[i] - m);
    #pragma unroll
    for (int o = 16; o; o >>= 1) s += __shfl_xor_sync(0xffffffffu, s, o);
    if ((tid & 31) == 0) red[tid >> 5] = s;
    __syncthreads();
    s = red[0];
    #pragma unroll
    for (int i = 1; i < 8; i++) s += red[i];

    const float inv = 1.0f / s;
    for (int i = tid; i < L; i += 256) {
        float e = expf(p[i] - m) * inv;
        __nv_bfloat16 h = __float2bfloat16(e);
        oh[i] = h;
        ol[i] = __float2bfloat16(e - __bfloat162float(h));
    }
    const __nv_bfloat16 z = __float2bfloat16(0.0f);
    for (int i = L + tid; i < S_; i += 256) { oh[i] = z; ol[i] = z; }
}

// ---------------------------------------------------------------------------
// Inputs (metadata order): x, wq, wk, wv, wo, freqs_cos, freqs_sin
// ---------------------------------------------------------------------------
extern "C" void kernel_launch(void* const* d_in, const int* in_sizes, int n_in,
                              void* d_out, int out_size)
{
    const float* x  = (const float*)d_in[0];
    const float* wq = (const float*)d_in[1];
    const float* wk = (const float*)d_in[2];
    const float* wv = (const float*)d_in[3];
    const float* wo = (const float*)d_in[4];
    const float* fc = (const float*)d_in[5];
    const float* fs = (const float*)d_in[6];
    float* out = (float*)d_out;

    __nv_bfloat16 *xhi, *xlo, *wqhi, *wqlo, *wkhi, *wklo, *wvhi, *wvlo, *wohi, *wolo;
    __nv_bfloat16 *qhi, *qlo, *khi, *klo, *vthi, *vtlo, *phi, *plo, *ahi, *alo;
    float *qf, *kf, *vf, *sp;
    cudaGetSymbolAddress((void**)&xhi,  g_xhi);  cudaGetSymbolAddress((void**)&xlo,  g_xlo);
    cudaGetSymbolAddress((void**)&wqhi, g_wqhi); cudaGetSymbolAddress((void**)&wqlo, g_wqlo);
    cudaGetSymbolAddress((void**)&wkhi, g_wkhi); cudaGetSymbolAddress((void**)&wklo, g_wklo);
    cudaGetSymbolAddress((void**)&wvhi, g_wvhi); cudaGetSymbolAddress((void**)&wvlo, g_wvlo);
    cudaGetSymbolAddress((void**)&wohi, g_wohi); cudaGetSymbolAddress((void**)&wolo, g_wolo);
    cudaGetSymbolAddress((void**)&qf, g_qf);
    cudaGetSymbolAddress((void**)&kf, g_kf);
    cudaGetSymbolAddress((void**)&vf, g_vf);
    cudaGetSymbolAddress((void**)&qhi, g_qhi);   cudaGetSymbolAddress((void**)&qlo, g_qlo);
    cudaGetSymbolAddress((void**)&khi, g_khi);   cudaGetSymbolAddress((void**)&klo, g_klo);
    cudaGetSymbolAddress((void**)&vthi, g_vthi); cudaGetSymbolAddress((void**)&vtlo, g_vtlo);
    cudaGetSymbolAddress((void**)&sp, g_sc);
    cudaGetSymbolAddress((void**)&phi, g_phi);   cudaGetSymbolAddress((void**)&plo, g_plo);
    cudaGetSymbolAddress((void**)&ahi, g_ahi);   cudaGetSymbolAddress((void**)&alo, g_alo);

    cudaFuncSetAttribute(gemm_mma<0>, cudaFuncAttributeMaxDynamicSharedMemorySize, SMEM_SZ);
    cudaFuncSetAttribute(gemm_mma<1>, cudaFuncAttributeMaxDynamicSharedMemorySize, SMEM_SZ);

    const float scale = 0.08838834764831845f;  // 1/sqrt(128)

    // 1) split inputs into bf16 hi/lo
    split_k<<<16384, 256>>>((const float4*)x,  (__nv_bfloat162*)xhi,  (__nv_bfloat162*)xlo,  4194304);
    split_k<<<16384, 256>>>((const float4*)wq, (__nv_bfloat162*)wqhi, (__nv_bfloat162*)wqlo, 4194304);
    split_k<<<4096,  256>>>((const float4*)wk, (__nv_bfloat162*)wkhi, (__nv_bfloat162*)wklo, 1048576);
    split_k<<<4096,  256>>>((const float4*)wv, (__nv_bfloat162*)wvhi, (__nv_bfloat162*)wvlo, 1048576);
    split_k<<<16384, 256>>>((const float4*)wo, (__nv_bfloat162*)wohi, (__nv_bfloat162*)wolo, 4194304);

    // 2) projections (fp32 out)
    gemm_mma<0><<<dim3(32, 32, 1), 256, SMEM_SZ>>>(
        xhi, xlo, wqhi, wqlo, qf, nullptr, nullptr,
        DIM_, DIM_, DIM_, DIM_, 1, 1, 0, 0, 0, 0, 0, 0, 1.0f, 0, 0);
    gemm_mma<0><<<dim3(8, 32, 1), 256, SMEM_SZ>>>(
        xhi, xlo, wkhi, wklo, kf, nullptr, nullptr,
        DIM_, DIM_, DIM_, NKV_ * HD_, 1, 1, 0, 0, 0, 0, 0, 0, 1.0f, 0, 0);
    gemm_mma<0><<<dim3(8, 32, 1), 256, SMEM_SZ>>>(
        xhi, xlo, wvhi, wvlo, vf, nullptr, nullptr,
        DIM_, DIM_, DIM_, NKV_ * HD_, 1, 1, 0, 0, 0, 0, 0, 0, 1.0f, 0, 0);

    // 3) RoPE + split (q, k); V transpose + split
    rope_split_k<<<32768, 256>>>(qf, NH_, fc, fs, qhi, qlo);
    rope_split_k<<<8192, 256>>>(kf, NKV_, fc, fs, khi, klo);
    tsplit_v_k<<<dim3(S_ / 32, HD_ / 32, B_ * NKV_), 256>>>(vf, vthi, vtlo);

    // 4) scores = scale * Q K^T  (causal tile skip)
    gemm_mma<0><<<dim3(16, 16, B_ * NH_), 256, SMEM_SZ>>>(
        qhi, qlo, khi, klo, sp, nullptr, nullptr,
        HD_, NH_ * HD_, NKV_ * HD_, S_,
        NH_, 4,
        (long long)HD_, (long long)S_ * NH_ * HD_,
        (long long)HD_, (long long)S_ * NKV_ * HD_,
        (long long)S_ * S_, (long long)NH_ * S_ * S_,
        scale, 1, 0);

    // 5) softmax -> split probs
    softmax_k<<<B_ * NH_ * S_, 256>>>(sp, phi, plo);

    // 6) attn = P V  (K capped causally; split epilogue)
    gemm_mma<1><<<dim3(1, 16, B_ * NH_), 256, SMEM_SZ>>>(
        phi, plo, vthi, vtlo, nullptr, ahi, alo,
        S_, S_, S_, NH_ * HD_,
        NH_, 4,
        (long long)S_ * S_, (long long)NH_ * S_ * S_,
        (long long)HD_ * S_, (long long)NKV_ * HD_ * S_,
        (long long)HD_, (long long)S_ * NH_ * HD_,
        1.0f, 0, 1);

    // 7) output projection
    gemm_mma<0><<<dim3(32, 32, 1), 256, SMEM_SZ>>>(
        ahi, alo, wohi, wolo, out, nullptr, nullptr,
        DIM_, DIM_, DIM_, DIM_, 1, 1, 0, 0, 0, 0, 0, 0, 1.0f, 0, 0);
}

// round 6
// speedup vs baseline: 4.5633x; 1.1221x over previous
#include <cuda_runtime.h>
#include <cuda_bf16.h>
#include <math.h>

// Problem constants
constexpr int B_   = 2;
constexpr int S_   = 2048;
constexpr int DIM_ = 4096;
constexpr int NH_  = 32;
constexpr int NKV_ = 8;
constexpr int HD_  = 128;

// ---------------------------------------------------------------------------
// Scratch (module-scope device arrays; allocation-free at launch time)
// ---------------------------------------------------------------------------
__device__ __nv_bfloat16 g_xhi[16777216],  g_xlo[16777216];     // x split
__device__ __nv_bfloat16 g_wqhi[16777216], g_wqlo[16777216];
__device__ __nv_bfloat16 g_wkhi[4194304],  g_wklo[4194304];
__device__ __nv_bfloat16 g_wvhi[4194304],  g_wvlo[4194304];
__device__ __nv_bfloat16 g_wohi[16777216], g_wolo[16777216];
__device__ float         g_qf[16777216];                        // q fp32 (pre-rope)
__device__ float         g_kf[4194304];
__device__ float         g_vf[4194304];
__device__ __nv_bfloat16 g_qhi[16777216], g_qlo[16777216];      // post-rope split
__device__ __nv_bfloat16 g_khi[4194304],  g_klo[4194304];
__device__ __nv_bfloat16 g_vthi[4194304], g_vtlo[4194304];      // V transposed [b,kv,d,s]
__device__ float         g_sc[268435456];                       // scores fp32 [b,h,q,k]
__device__ __nv_bfloat16 g_phi[268435456], g_plo[268435456];    // probs split
__device__ __nv_bfloat16 g_ahi[16777216],  g_alo[16777216];     // attn split [b,s,h,d]

// ---------------------------------------------------------------------------
// PTX helpers — sm_80-era only (compute_103 virtual arch: NO tcgen05)
// ---------------------------------------------------------------------------
__device__ __forceinline__ unsigned smem_u32(const void* p) {
    return (unsigned)__cvta_generic_to_shared(p);
}
__device__ __forceinline__ void cpa16(unsigned dst, const void* src) {
    asm volatile("cp.async.cg.shared.global [%0], [%1], 16;" :: "r"(dst), "l"(src) : "memory");
}
__device__ __forceinline__ void cpa_commit() {
    asm volatile("cp.async.commit_group;" ::: "memory");
}
__device__ __forceinline__ void cpa_wait1() {
    asm volatile("cp.async.wait_group 1;" ::: "memory");
}
__device__ __forceinline__ void cpa_wait0() {
    asm volatile("cp.async.wait_group 0;" ::: "memory");
}
__device__ __forceinline__ void ldsm4(unsigned* r, unsigned a) {
    asm volatile("ldmatrix.sync.aligned.m8n8.x4.shared.b16 {%0,%1,%2,%3}, [%4];"
                 : "=r"(r[0]), "=r"(r[1]), "=r"(r[2]), "=r"(r[3]) : "r"(a));
}
__device__ __forceinline__ void mma16816(float* c, const unsigned* a, const unsigned* b) {
    asm volatile("mma.sync.aligned.m16n8k16.row.col.f32.bf16.bf16.f32 "
                 "{%0,%1,%2,%3}, {%4,%5,%6,%7}, {%8,%9}, {%0,%1,%2,%3};"
                 : "+f"(c[0]), "+f"(c[1]), "+f"(c[2]), "+f"(c[3])
                 : "r"(a[0]), "r"(a[1]), "r"(a[2]), "r"(a[3]), "r"(b[0]), "r"(b[1]));
}

// SMEM geometry: rows of 32 bf16 (64B) padded to 80B pitch -> conflict-free
// ldmatrix (8-row phase banks: r*20 mod 32 all distinct) and 16B-aligned cp.async.
constexpr int PITCH   = 80;
constexpr int SUBT    = 128 * PITCH;   // 10240 B per operand subtile
constexpr int STAGE   = 4 * SUBT;      // Ahi|Alo|Bhi|Blo = 40960 B
constexpr int SMEM_SZ = 2 * STAGE;     // double buffered = 81920 B

// ---------------------------------------------------------------------------
// bf16 split GEMM via mma.sync: C[m,n] = scale * sum_k A[m,k]*B[n,k]
//   A = Ahi+Alo, B = Bhi+Blo (hi/lo split of fp32), both K-major [rows, K].
//   3 passes accumulated in fp32 regs: hi*hi + hi*lo + lo*hi.
//   EPI=0: fp32 C.  EPI=1: hi/lo bf16 split C.
//   causal=1: skip tiles above diagonal.  kcap=1: K capped at bm0+128.
//   __launch_bounds__(256, 2): 2 CTAs/SM to hide the 2-stage barrier bubble.
// ---------------------------------------------------------------------------
template <int EPI>
__global__ __launch_bounds__(256, 2)
void gemm_mma(const __nv_bfloat16* __restrict__ Ahi, const __nv_bfloat16* __restrict__ Alo,
              const __nv_bfloat16* __restrict__ Bhi, const __nv_bfloat16* __restrict__ Blo,
              float* __restrict__ Cf,
              __nv_bfloat16* __restrict__ Chi, __nv_bfloat16* __restrict__ Clo,
              int K, int lda, int ldb, int ldc,
              int zdiv, int bdiv,
              long long sA1, long long sA2, long long sB1, long long sB2,
              long long sC1, long long sC2,
              float scale, int causal, int kcap)
{
    const int bm0 = blockIdx.y * 128;
    const int bn0 = blockIdx.x * 128;
    if (causal && bn0 > bm0) return;

    const int z  = blockIdx.z;
    const int z2 = z / zdiv;
    const int z1 = z - z2 * zdiv;
    const __nv_bfloat16* Ah = Ahi + z2 * sA2 + (long long)z1 * sA1;
    const __nv_bfloat16* Al = Alo + z2 * sA2 + (long long)z1 * sA1;
    const __nv_bfloat16* Bh = Bhi + z2 * sB2 + (long long)(z1 / bdiv) * sB1;
    const __nv_bfloat16* Bl = Blo + z2 * sB2 + (long long)(z1 / bdiv) * sB1;
    const long long coff = z2 * sC2 + (long long)z1 * sC1;

    extern __shared__ char smem[];
    const unsigned sb = smem_u32(smem);
    const int tid  = threadIdx.x;
    const int lane = tid & 31;
    const int wid  = tid >> 5;
    const int wm   = wid & 3;     // 4 warp-rows x 32
    const int wn   = wid >> 2;    // 2 warp-cols x 64

    int Keff = K;
    if (kcap) { int c = bm0 + 128; if (c < Keff) Keff = c; }
    const int nk = Keff >> 5;     // KC = 32

    auto stage = [&](int si) {
        const unsigned base = sb + (si & 1) * STAGE;
        const int kc = si * 32;
        #pragma unroll
        for (int it = 0; it < 8; it++) {
            const int sub = it >> 1;                 // 0:Ahi 1:Alo 2:Bhi 3:Blo
            const int w   = (tid + it * 256) & 511;
            const int row = w >> 2, seg = w & 3;     // 4 x 16B per 64B row
            const __nv_bfloat16* src;
            if      (sub == 0) src = Ah + (long long)(bm0 + row) * lda + kc + seg * 8;
            else if (sub == 1) src = Al + (long long)(bm0 + row) * lda + kc + seg * 8;
            else if (sub == 2) src = Bh + (long long)(bn0 + row) * ldb + kc + seg * 8;
            else               src = Bl + (long long)(bn0 + row) * ldb + kc + seg * 8;
            cpa16(base + sub * SUBT + row * PITCH + seg * 16, src);
        }
    };

    float acc[2][8][4];
    #pragma unroll
    for (int i = 0; i < 2; i++)
        #pragma unroll
        for (int j = 0; j < 8; j++)
            #pragma unroll
            for (int e = 0; e < 4; e++) acc[i][j][e] = 0.0f;

    stage(0); cpa_commit();
    stage(1); cpa_commit();

    // ldmatrix lane address components (constant across chunks)
    const int arow = wm * 32 + (lane & 15);          // + mt*16
    const int asel = (lane >> 4);                    // 16B chunk within kstep
    const int brow = wn * 64 + (lane & 7) + ((lane >> 4) << 3);  // + pair*16
    const int bsel = (lane >> 3) & 1;

    for (int i = 0; i < nk; i++) {
        if (i + 1 < nk) cpa_wait1(); else cpa_wait0();
        __syncthreads();
        const unsigned base = sb + (i & 1) * STAGE;

        #pragma unroll
        for (int ks = 0; ks < 2; ks++) {
            unsigned ah[2][4], al[2][4];
            #pragma unroll
            for (int mt = 0; mt < 2; mt++) {
                const unsigned off = (arow + mt * 16) * PITCH + (ks * 2 + asel) * 16;
                ldsm4(ah[mt], base + off);
                ldsm4(al[mt], base + SUBT + off);
            }
            #pragma unroll
            for (int pr = 0; pr < 4; pr++) {
                unsigned bh[4], bl[4];
                const unsigned off = (brow + pr * 16) * PITCH + (ks * 2 + bsel) * 16;
                ldsm4(bh, base + 2 * SUBT + off);
                ldsm4(bl, base + 3 * SUBT + off);
                #pragma unroll
                for (int mt = 0; mt < 2; mt++)
                    #pragma unroll
                    for (int hf = 0; hf < 2; hf++) {
                        float* c = acc[mt][pr * 2 + hf];
                        mma16816(c, ah[mt], &bh[hf * 2]);
                        mma16816(c, ah[mt], &bl[hf * 2]);
                        mma16816(c, al[mt], &bh[hf * 2]);
                    }
            }
        }
        __syncthreads();
        if (i + 2 < nk) { stage(i + 2); cpa_commit(); }
    }

    // Epilogue: register accumulators -> global (float2 / bf16x2 stores)
    const int er = bm0 + wm * 32 + (lane >> 2);
    const int ec = bn0 + wn * 64 + (lane & 3) * 2;
    #pragma unroll
    for (int mt = 0; mt < 2; mt++)
        #pragma unroll
        for (int nt = 0; nt < 8; nt++) {
            const float* c = acc[mt][nt];
            const int row = er + mt * 16;
            const int col = ec + nt * 8;
            const long long gi0 = coff + (long long)row * ldc + col;
            const long long gi1 = coff + (long long)(row + 8) * ldc + col;
            if (EPI == 0) {
                *(float2*)(Cf + gi0) = make_float2(c[0] * scale, c[1] * scale);
                *(float2*)(Cf + gi1) = make_float2(c[2] * scale, c[3] * scale);
            } else {
                float v0 = c[0] * scale, v1 = c[1] * scale;
                float v2 = c[2] * scale, v3 = c[3] * scale;
                __nv_bfloat16 h0 = __float2bfloat16(v0), h1 = __float2bfloat16(v1);
                __nv_bfloat16 h2 = __float2bfloat16(v2), h3 = __float2bfloat16(v3);
                *(__nv_bfloat162*)(Chi + gi0) = __halves2bfloat162(h0, h1);
                *(__nv_bfloat162*)(Chi + gi1) = __halves2bfloat162(h2, h3);
                *(__nv_bfloat162*)(Clo + gi0) = __halves2bfloat162(
                    __float2bfloat16(v0 - __bfloat162float(h0)),
                    __float2bfloat16(v1 - __bfloat162float(h1)));
                *(__nv_bfloat162*)(Clo + gi1) = __halves2bfloat162(
                    __float2bfloat16(v2 - __bfloat162float(h2)),
                    __float2bfloat16(v3 - __bfloat162float(h3)));
            }
        }
}

// ---------------------------------------------------------------------------
// Elementwise fp32 -> (hi, lo) bf16 split
// ---------------------------------------------------------------------------
__global__ __launch_bounds__(256)
void split_k(const float4* __restrict__ s, __nv_bfloat162* __restrict__ h2,
             __nv_bfloat162* __restrict__ l2, int n4)
{
    int i = blockIdx.x * 256 + threadIdx.x;
    if (i >= n4) return;
    float4 v = s[i];
    __nv_bfloat16 hx = __float2bfloat16(v.x), hy = __float2bfloat16(v.y);
    __nv_bfloat16 hz = __float2bfloat16(v.z), hw = __float2bfloat16(v.w);
    h2[2 * i]     = __halves2bfloat162(hx, hy);
    h2[2 * i + 1] = __halves2bfloat162(hz, hw);
    l2[2 * i]     = __halves2bfloat162(__float2bfloat16(v.x - __bfloat162float(hx)),
                                       __float2bfloat16(v.y - __bfloat162float(hy)));
    l2[2 * i + 1] = __halves2bfloat162(__float2bfloat16(v.z - __bfloat162float(hz)),
                                       __float2bfloat16(v.w - __bfloat162float(hw)));
}

// ---------------------------------------------------------------------------
// RoPE + split: reads fp32 [B,S,nh,HD], writes hi/lo bf16 same layout
// ---------------------------------------------------------------------------
__global__ __launch_bounds__(256)
void rope_split_k(const float* __restrict__ t, int nh,
                  const float* __restrict__ cs, const float* __restrict__ sn,
                  __nv_bfloat16* __restrict__ hi, __nv_bfloat16* __restrict__ lo)
{
    long long idx = (long long)blockIdx.x * 256 + threadIdx.x;
    const long long total = (long long)B_ * S_ * nh * (HD_ / 2);
    if (idx >= total) return;
    const int i = (int)(idx & 63);
    long long r = idx >> 6;
    const int h = (int)(r % nh); r /= nh;
    const int s = (int)(r % S_);
    const long long b = r / S_;

    const float c  = cs[s * 64 + i];
    const float si = sn[s * 64 + i];
    const long long off = (((b * S_ + s) * nh + h) * (long long)HD_) + 2 * i;
    const float t0 = t[off], t1 = t[off + 1];
    const float o0 = t0 * c - t1 * si;
    const float o1 = t0 * si + t1 * c;
    __nv_bfloat16 h0 = __float2bfloat16(o0);
    __nv_bfloat16 h1 = __float2bfloat16(o1);
    hi[off] = h0;     lo[off]     = __float2bfloat16(o0 - __bfloat162float(h0));
    hi[off + 1] = h1; lo[off + 1] = __float2bfloat16(o1 - __bfloat162float(h1));
}

// ---------------------------------------------------------------------------
// V transpose + split: vf32 [b,s,kv,d] -> vt hi/lo [b,kv,d,s]
// ---------------------------------------------------------------------------
__global__ __launch_bounds__(256)
void tsplit_v_k(const float* __restrict__ v,
                __nv_bfloat16* __restrict__ hi, __nv_bfloat16* __restrict__ lo)
{
    __shared__ float tile[32][33];
    const int bz = blockIdx.z;
    const int b = bz >> 3, kv = bz & 7;
    const int s0 = blockIdx.x * 32, d0 = blockIdx.y * 32;
    const int tx = threadIdx.x & 31, ty = threadIdx.x >> 5;

    #pragma unroll
    for (int j = 0; j < 4; j++) {
        int s = s0 + ty + j * 8;
        tile[ty + j * 8][tx] = v[((size_t)(b * S_ + s) * NKV_ + kv) * HD_ + d0 + tx];
    }
    __syncthreads();
    #pragma unroll
    for (int j = 0; j < 4; j++) {
        int d = d0 + ty + j * 8;
        float val = tile[tx][ty + j * 8];
        size_t o = ((size_t)(b * NKV_ + kv) * HD_ + d) * S_ + s0 + tx;
        __nv_bfloat16 h = __float2bfloat16(val);
        hi[o] = h;
        lo[o] = __float2bfloat16(val - __bfloat162float(h));
    }
}

// ---------------------------------------------------------------------------
// Causal softmax: fp32 scores row -> hi/lo bf16 probs. Zero-fills only up to
// the next 128-col boundary — the PV GEMM's kcap never reads beyond it.
// ---------------------------------------------------------------------------
__global__ __launch_bounds__(256)
void softmax_k(const float* __restrict__ sc,
               __nv_bfloat16* __restrict__ phi, __nv_bfloat16* __restrict__ plo)
{
    const long long row = blockIdx.x;
    const int q = (int)(row % S_);
    const float* p = sc + row * (long long)S_;
    __nv_bfloat16* oh = phi + row * (long long)S_;
    __nv_bfloat16* ol = plo + row * (long long)S_;
    const int L = q + 1;
    const int tid = threadIdx.x;
    __shared__ float red[8];

    float m = -1e30f;
    for (int i = tid; i < L; i += 256) m = fmaxf(m, p[i]);
    #pragma unroll
    for (int o = 16; o; o >>= 1) m = fmaxf(m, __shfl_xor_sync(0xffffffffu, m, o));
    if ((tid & 31) == 0) red[tid >> 5] = m;
    __syncthreads();
    m = red[0];
    #pragma unroll
    for (int i = 1; i < 8; i++) m = fmaxf(m, red[i]);
    __syncthreads();

    float s = 0.0f;
    for (int i = tid; i < L; i += 256) s += expf(p[i] - m);
    #pragma unroll
    for (int o = 16; o; o >>= 1) s += __shfl_xor_sync(0xffffffffu, s, o);
    if ((tid & 31) == 0) red[tid >> 5] = s;
    __syncthreads();
    s = red[0];
    #pragma unroll
    for (int i = 1; i < 8; i++) s += red[i];

    const float inv = 1.0f / s;
    for (int i = tid; i < L; i += 256) {
        float e = expf(p[i] - m) * inv;
        __nv_bfloat16 h = __float2bfloat16(e);
        oh[i] = h;
        ol[i] = __float2bfloat16(e - __bfloat162float(h));
    }
    const int zend = ((q >> 7) + 1) << 7;   // next 128 boundary (= PV kcap limit)
    const __nv_bfloat16 z = __float2bfloat16(0.0f);
    for (int i = L + tid; i < zend; i += 256) { oh[i] = z; ol[i] = z; }
}

// ---------------------------------------------------------------------------
// Inputs (metadata order): x, wq, wk, wv, wo, freqs_cos, freqs_sin
// ---------------------------------------------------------------------------
extern "C" void kernel_launch(void* const* d_in, const int* in_sizes, int n_in,
                              void* d_out, int out_size)
{
    const float* x  = (const float*)d_in[0];
    const float* wq = (const float*)d_in[1];
    const float* wk = (const float*)d_in[2];
    const float* wv = (const float*)d_in[3];
    const float* wo = (const float*)d_in[4];
    const float* fc = (const float*)d_in[5];
    const float* fs = (const float*)d_in[6];
    float* out = (float*)d_out;

    __nv_bfloat16 *xhi, *xlo, *wqhi, *wqlo, *wkhi, *wklo, *wvhi, *wvlo, *wohi, *wolo;
    __nv_bfloat16 *qhi, *qlo, *khi, *klo, *vthi, *vtlo, *phi, *plo, *ahi, *alo;
    float *qf, *kf, *vf, *sp;
    cudaGetSymbolAddress((void**)&xhi,  g_xhi);  cudaGetSymbolAddress((void**)&xlo,  g_xlo);
    cudaGetSymbolAddress((void**)&wqhi, g_wqhi); cudaGetSymbolAddress((void**)&wqlo, g_wqlo);
    cudaGetSymbolAddress((void**)&wkhi, g_wkhi); cudaGetSymbolAddress((void**)&wklo, g_wklo);
    cudaGetSymbolAddress((void**)&wvhi, g_wvhi); cudaGetSymbolAddress((void**)&wvlo, g_wvlo);
    cudaGetSymbolAddress((void**)&wohi, g_wohi); cudaGetSymbolAddress((void**)&wolo, g_wolo);
    cudaGetSymbolAddress((void**)&qf, g_qf);
    cudaGetSymbolAddress((void**)&kf, g_kf);
    cudaGetSymbolAddress((void**)&vf, g_vf);
    cudaGetSymbolAddress((void**)&qhi, g_qhi);   cudaGetSymbolAddress((void**)&qlo, g_qlo);
    cudaGetSymbolAddress((void**)&khi, g_khi);   cudaGetSymbolAddress((void**)&klo, g_klo);
    cudaGetSymbolAddress((void**)&vthi, g_vthi); cudaGetSymbolAddress((void**)&vtlo, g_vtlo);
    cudaGetSymbolAddress((void**)&sp, g_sc);
    cudaGetSymbolAddress((void**)&phi, g_phi);   cudaGetSymbolAddress((void**)&plo, g_plo);
    cudaGetSymbolAddress((void**)&ahi, g_ahi);   cudaGetSymbolAddress((void**)&alo, g_alo);

    cudaFuncSetAttribute(gemm_mma<0>, cudaFuncAttributeMaxDynamicSharedMemorySize, SMEM_SZ);
    cudaFuncSetAttribute(gemm_mma<1>, cudaFuncAttributeMaxDynamicSharedMemorySize, SMEM_SZ);

    const float scale = 0.08838834764831845f;  // 1/sqrt(128)

    // 1) split inputs into bf16 hi/lo
    split_k<<<16384, 256>>>((const float4*)x,  (__nv_bfloat162*)xhi,  (__nv_bfloat162*)xlo,  4194304);
    split_k<<<16384, 256>>>((const float4*)wq, (__nv_bfloat162*)wqhi, (__nv_bfloat162*)wqlo, 4194304);
    split_k<<<4096,  256>>>((const float4*)wk, (__nv_bfloat162*)wkhi, (__nv_bfloat162*)wklo, 1048576);
    split_k<<<4096,  256>>>((const float4*)wv, (__nv_bfloat162*)wvhi, (__nv_bfloat162*)wvlo, 1048576);
    split_k<<<16384, 256>>>((const float4*)wo, (__nv_bfloat162*)wohi, (__nv_bfloat162*)wolo, 4194304);

    // 2) projections (fp32 out)
    gemm_mma<0><<<dim3(32, 32, 1), 256, SMEM_SZ>>>(
        xhi, xlo, wqhi, wqlo, qf, nullptr, nullptr,
        DIM_, DIM_, DIM_, DIM_, 1, 1, 0, 0, 0, 0, 0, 0, 1.0f, 0, 0);
    gemm_mma<0><<<dim3(8, 32, 1), 256, SMEM_SZ>>>(
        xhi, xlo, wkhi, wklo, kf, nullptr, nullptr,
        DIM_, DIM_, DIM_, NKV_ * HD_, 1, 1, 0, 0, 0, 0, 0, 0, 1.0f, 0, 0);
    gemm_mma<0><<<dim3(8, 32, 1), 256, SMEM_SZ>>>(
        xhi, xlo, wvhi, wvlo, vf, nullptr, nullptr,
        DIM_, DIM_, DIM_, NKV_ * HD_, 1, 1, 0, 0, 0, 0, 0, 0, 1.0f, 0, 0);

    // 3) RoPE + split (q, k); V transpose + split
    rope_split_k<<<32768, 256>>>(qf, NH_, fc, fs, qhi, qlo);
    rope_split_k<<<8192, 256>>>(kf, NKV_, fc, fs, khi, klo);
    tsplit_v_k<<<dim3(S_ / 32, HD_ / 32, B_ * NKV_), 256>>>(vf, vthi, vtlo);

    // 4) scores = scale * Q K^T  (causal tile skip)
    gemm_mma<0><<<dim3(16, 16, B_ * NH_), 256, SMEM_SZ>>>(
        qhi, qlo, khi, klo, sp, nullptr, nullptr,
        HD_, NH_ * HD_, NKV_ * HD_, S_,
        NH_, 4,
        (long long)HD_, (long long)S_ * NH_ * HD_,
        (long long)HD_, (long long)S_ * NKV_ * HD_,
        (long long)S_ * S_, (long long)NH_ * S_ * S_,
        scale, 1, 0);

    // 5) softmax -> split probs
    softmax_k<<<B_ * NH_ * S_, 256>>>(sp, phi, plo);

    // 6) attn = P V  (K capped causally; split epilogue)
    gemm_mma<1><<<dim3(1, 16, B_ * NH_), 256, SMEM_SZ>>>(
        phi, plo, vthi, vtlo, nullptr, ahi, alo,
        S_, S_, S_, NH_ * HD_,
        NH_, 4,
        (long long)S_ * S_, (long long)NH_ * S_ * S_,
        (long long)HD_ * S_, (long long)NKV_ * HD_ * S_,
        (long long)HD_, (long long)S_ * NH_ * HD_,
        1.0f, 0, 1);

    // 7) output projection
    gemm_mma<0><<<dim3(32, 32, 1), 256, SMEM_SZ>>>(
        ahi, alo, wohi, wolo, out, nullptr, nullptr,
        DIM_, DIM_, DIM_, DIM_, 1, 1, 0, 0, 0, 0, 0, 0, 1.0f, 0, 0);
}